// round 16
// baseline (speedup 1.0000x reference)
#include <cuda_runtime.h>
#include <cuda_bf16.h>
#include <cstdint>

#define BATCH 4
#define CH    64
#define H     256
#define WID   256
#define HW    (H*WID)
#define CHW   (CH*HW)
#define C2ROWS 257          // center rows -1..255 stored at index yc+1
#define NPX   128           // pixels per block (N tile)
#define RS    24            // smem row stride in halves (48B -> conflict-free ldmatrix)

// scratch (allocation-free: __device__ globals)
__device__ float g_s[BATCH*HW];                    // per-pixel vertical shift s
__device__ float g_C2[BATCH*CH*C2ROWS*WID];        // conv3x3(x2) at rows -1..255
// channel-last bf16 hi/lo inputs: [b][y][x][c]
__device__ __align__(16) __nv_bfloat16 g_Xh[BATCH*HW*CH];
__device__ __align__(16) __nv_bfloat16 g_Xl[BATCH*HW*CH];
__device__ __align__(16) __nv_bfloat16 g_Zh[BATCH*HW*CH];
__device__ __align__(16) __nv_bfloat16 g_Zl[BATCH*HW*CH];
// weights as per-lane mma A fragments: [cc][tap][slice16][lane] -> uint4
__device__ __align__(16) __nv_bfloat16 g_Wah[4*9*4*32*8];
__device__ __align__(16) __nv_bfloat16 g_Wal[4*9*4*32*8];

// ---------------------------------------------------------------------------
__device__ __forceinline__ void mma16816(float* d, const uint32_t* a, uint32_t b0, uint32_t b1) {
    asm volatile(
        "mma.sync.aligned.m16n8k16.row.col.f32.bf16.bf16.f32 "
        "{%0,%1,%2,%3}, {%4,%5,%6,%7}, {%8,%9}, {%0,%1,%2,%3};\n"
        : "+f"(d[0]), "+f"(d[1]), "+f"(d[2]), "+f"(d[3])
        : "r"(a[0]), "r"(a[1]), "r"(a[2]), "r"(a[3]), "r"(b0), "r"(b1));
}

__device__ __forceinline__ void ldsm4(uint32_t* r, uint32_t addr) {
    asm volatile("ldmatrix.sync.aligned.m8n8.x4.shared.b16 {%0,%1,%2,%3}, [%4];"
        : "=r"(r[0]), "=r"(r[1]), "=r"(r[2]), "=r"(r[3]) : "r"(addr));
}

// ---------------------------------------------------------------------------
// Kernel W: split weights into bf16 hi/lo, scatter into per-lane A fragments
// ---------------------------------------------------------------------------
__global__ __launch_bounds__(256) void wt_kernel(const float* __restrict__ Wg) {
    int i = blockIdx.x * 256 + threadIdx.x;
    if (i >= CH*CH*9) return;
    int oc  = i / (CH*9);
    int rem = i - oc*CH*9;
    int c   = rem / 9;
    int tap = rem - c*9;
    float wv = Wg[i];
    __nv_bfloat16 h = __float2bfloat16(wv);
    __nv_bfloat16 l = __float2bfloat16(wv - __bfloat162float(h));

    int sl   = oc >> 4;           // m16 slice index 0..3
    int ocw  = oc & 15;
    int g    = ocw & 7;
    int hi8  = ocw >> 3;
    int cc   = c >> 4;
    int cp   = c & 15;
    int tig  = (cp >> 1) & 3;
    int khalf= cp >> 3;
    int pair = cp & 1;
    int reg  = hi8 + 2*khalf;
    int lane = g*4 + tig;
    int dst  = ((((cc*9 + tap)*4 + sl)*32 + lane)*4 + reg)*2 + pair;
    g_Wah[dst] = h;
    g_Wal[dst] = l;
}

// ---------------------------------------------------------------------------
// Kernel A (coalesced): 8 threads per pixel, each owning 8 channels.
// Channel-max via shfl over the 8-lane group; channel-last writes are fully
// coalesced (8 lanes x 16B = 128B contiguous per pixel per tensor).
// ---------------------------------------------------------------------------
__global__ __launch_bounds__(256) void prep_kernel(const float* __restrict__ X) {
    long idx = (long)blockIdx.x * 256 + threadIdx.x;
    if (idx >= (long)BATCH*HW*8) return;
    int pix = (int)(idx >> 3);
    int cg  = (int)(idx & 7);      // channel group: channels [cg*8, cg*8+8)
    int b   = pix / HW;
    int rem = pix - b*HW;
    int y   = rem / WID;
    int x   = rem - y*WID;

    const float* Xpix = X + (long)b*CHW + y*WID + x;
    const float* Xc = Xpix + (long)cg*8*HW;

    float a[8];
    #pragma unroll
    for (int j = 0; j < 8; j++) a[j] = __ldg(Xc + (long)j*HW);

    float m = a[0];
    #pragma unroll
    for (int j = 1; j < 8; j++) m = fmaxf(m, a[j]);
    m = fmaxf(m, __shfl_xor_sync(0xffffffffu, m, 1));
    m = fmaxf(m, __shfl_xor_sync(0xffffffffu, m, 2));
    m = fmaxf(m, __shfl_xor_sync(0xffffffffu, m, 4));

    float depth = fminf(fmaxf(m, 1.0f), 50.0f);
    float s = 50.0f / (2.0f * depth);
    if (cg == 0) g_s[pix] = s;

    float ys = (float)y - s;
    float fy = floorf(ys);
    int   y0 = (int)fy;
    float w1 = ys - fy;
    float w0 = 1.0f - w1;

    bool ok0 = (y0   >= 0) && (y0   < H);
    bool ok1 = (y0+1 >= 0) && (y0+1 < H);
    const float* P0 = X + (long)b*CHW + (long)(ok0 ? y0   : 0)*WID + x + (long)cg*8*HW;
    const float* P1 = X + (long)b*CHW + (long)(ok1 ? y0+1 : 0)*WID + x + (long)cg*8*HW;

    __nv_bfloat162 xh[4], xl[4], zh[4], zl[4];
    #pragma unroll
    for (int j = 0; j < 4; j++) {
        float a0 = a[2*j], a1 = a[2*j+1];
        float p0 = ok0 ? __ldg(P0 + (long)(2*j)*HW)   : 0.0f;
        float p1 = ok0 ? __ldg(P0 + (long)(2*j+1)*HW) : 0.0f;
        float q0 = ok1 ? __ldg(P1 + (long)(2*j)*HW)   : 0.0f;
        float q1 = ok1 ? __ldg(P1 + (long)(2*j+1)*HW) : 0.0f;
        float v0 = w0*p0 + w1*q0;
        float v1 = w0*p1 + w1*q1;

        __nv_bfloat16 ah0 = __float2bfloat16(a0);
        __nv_bfloat16 ah1 = __float2bfloat16(a1);
        __nv_bfloat16 vh0 = __float2bfloat16(v0);
        __nv_bfloat16 vh1 = __float2bfloat16(v1);
        xh[j] = __nv_bfloat162(ah0, ah1);
        xl[j] = __nv_bfloat162(__float2bfloat16(a0 - __bfloat162float(ah0)),
                               __float2bfloat16(a1 - __bfloat162float(ah1)));
        zh[j] = __nv_bfloat162(vh0, vh1);
        zl[j] = __nv_bfloat162(__float2bfloat16(v0 - __bfloat162float(vh0)),
                               __float2bfloat16(v1 - __bfloat162float(vh1)));
    }
    const long ob = (long)pix * CH + cg*8;
    *(uint4*)(g_Xh + ob) = *(uint4*)xh;
    *(uint4*)(g_Xl + ob) = *(uint4*)xl;
    *(uint4*)(g_Zh + ob) = *(uint4*)zh;
    *(uint4*)(g_Zl + ob) = *(uint4*)zl;
}

// ---------------------------------------------------------------------------
// Tensor-core conv: block = 64 oc x 128 px for one (b, center-row).
// 128 threads = 4 warps: ws2 = w&1 -> oc slice of 32, pxh = w>>1 -> px half.
// Warp = m32 x n64: per tap 4 LDG.128 (A) + 8 ldsm.x4 (B) feed 48 mmas
// -> ~1.0 L1 wavefront per mma. Single-buffered smem (37.4KB static).
// MODE 1: in = Zh/Zl, yc in [-1,255], store C2 at row index yc+1.
// MODE 0: in = Xh/Xl, yc in [0,255], fused interp+min epilogue -> Out.
// ---------------------------------------------------------------------------
template<int MODE>
__global__ __launch_bounds__(128, 3) void conv_mma_kernel(const __nv_bfloat16* __restrict__ Ih,
                                                          const __nv_bfloat16* __restrict__ Il,
                                                          float* __restrict__ Out) {
    __shared__ __align__(16) __nv_bfloat16 sBh[3][NPX+2][RS];
    __shared__ __align__(16) __nv_bfloat16 sBl[3][NPX+2][RS];

    const int t    = threadIdx.x;
    const int w    = t >> 5;
    const int lane = t & 31;
    const int g    = lane >> 2;
    const int tig  = lane & 3;
    const int ws2  = w & 1;            // oc slice of 32
    const int pxb  = (w >> 1) * 64;    // px half base

    const int x0 = blockIdx.x * NPX;
    const int yc = MODE ? ((int)blockIdx.y - 1) : (int)blockIdx.y;
    const int b  = blockIdx.z;

    float acc[2][8][4];                // [sub m16][nf over 64px][4]
    #pragma unroll
    for (int s2 = 0; s2 < 2; s2++)
        #pragma unroll
        for (int nf = 0; nf < 8; nf++)
            #pragma unroll
            for (int k = 0; k < 4; k++) acc[s2][nf][k] = 0.0f;

    const int rowadd = ((lane >> 4) & 1) * 8 + (lane & 7);
    const int coladd = ((lane >> 3) & 1) * 8;
    const uint32_t sbH = (uint32_t)__cvta_generic_to_shared(&sBh[0][0][0]);
    const uint32_t sbL = (uint32_t)__cvta_generic_to_shared(&sBl[0][0][0]);
    const uint32_t tb  = (uint32_t)(rowadd*RS + coladd) * 2;

    const long pixbase = (long)b*HW;
    const uint4* WAh = (const uint4*)g_Wah;
    const uint4* WAl = (const uint4*)g_Wal;

    for (int cc = 0; cc < 4; cc++) {
        __syncthreads();
        // ---- stage 16-ch chunk of 3 input rows (pure vector copy) ----
        {
            const uint4 z = make_uint4(0,0,0,0);
            for (int i = t; i < 3*(NPX+2); i += 128) {
                int r  = i / (NPX+2), px = i - r*(NPX+2);
                int row = yc + r - 1;
                int col = x0 + px - 1;
                uint4 h0 = z, h1 = z, l0 = z, l1 = z;
                if (row >= 0 && row < H && col >= 0 && col < WID) {
                    long off = ((pixbase + row*WID + col) * CH) + cc*16;
                    const uint4* ph = (const uint4*)(Ih + off);
                    const uint4* pl = (const uint4*)(Il + off);
                    h0 = __ldg(ph);  h1 = __ldg(ph + 1);
                    l0 = __ldg(pl);  l1 = __ldg(pl + 1);
                }
                *(uint4*)&sBh[r][px][0] = h0;
                *(uint4*)&sBh[r][px][8] = h1;
                *(uint4*)&sBl[r][px][0] = l0;
                *(uint4*)&sBl[r][px][8] = l1;
            }
        }
        __syncthreads();

        #pragma unroll
        for (int tap = 0; tap < 9; tap++) {
            const int ky = tap / 3;
            const int kx = tap - ky*3;

            uint32_t ah[2][4], al[2][4];
            #pragma unroll
            for (int s2 = 0; s2 < 2; s2++) {
                const int aidx = ((cc*9 + tap)*4 + ws2*2 + s2)*32 + lane;
                uint4 a4h = __ldg(WAh + aidx);
                uint4 a4l = __ldg(WAl + aidx);
                ah[s2][0]=a4h.x; ah[s2][1]=a4h.y; ah[s2][2]=a4h.z; ah[s2][3]=a4h.w;
                al[s2][0]=a4l.x; al[s2][1]=a4l.y; al[s2][2]=a4l.z; al[s2][3]=a4l.w;
            }

            #pragma unroll
            for (int P = 0; P < 4; P++) {
                const uint32_t off = tb
                    + (uint32_t)((ky*(NPX+2) + kx + pxb + P*16)*RS)*2;
                uint32_t bh[4], bl[4];
                ldsm4(bh, sbH + off);
                ldsm4(bl, sbL + off);
                const int nf0 = P*2, nf1 = P*2 + 1;
                #pragma unroll
                for (int s2 = 0; s2 < 2; s2++) {
                    mma16816(acc[s2][nf0], ah[s2], bh[0], bh[1]);
                    mma16816(acc[s2][nf0], ah[s2], bl[0], bl[1]);
                    mma16816(acc[s2][nf0], al[s2], bh[0], bh[1]);
                    mma16816(acc[s2][nf1], ah[s2], bh[2], bh[3]);
                    mma16816(acc[s2][nf1], ah[s2], bl[2], bl[3]);
                    mma16816(acc[s2][nf1], al[s2], bh[2], bh[3]);
                }
            }
        }
    }

    // ---- epilogue ----
    if (MODE == 1) {
        const int rr = yc + 1;            // 0..256
        #pragma unroll
        for (int s2 = 0; s2 < 2; s2++) {
            const int ocb = ws2*32 + s2*16;
            #pragma unroll
            for (int nf = 0; nf < 8; nf++) {
                const int col = pxb + (nf >> 1)*16 + (nf & 1)*8 + tig*2;
                float* o0 = g_C2 + (((long)(b*CH + ocb + g    ))*C2ROWS + rr)*WID + x0 + col;
                float* o1 = g_C2 + (((long)(b*CH + ocb + g + 8))*C2ROWS + rr)*WID + x0 + col;
                *(float2*)o0 = make_float2(acc[s2][nf][0], acc[s2][nf][1]);
                *(float2*)o1 = make_float2(acc[s2][nf][2], acc[s2][nf][3]);
            }
        }
    } else {
        #pragma unroll
        for (int nf = 0; nf < 8; nf++) {
            const int col = pxb + (nf >> 1)*16 + (nf & 1)*8 + tig*2;
            const int x = x0 + col;
            float2 sv = *(const float2*)&g_s[b*HW + yc*WID + x];

            float ysA = (float)yc - sv.x;
            float fA  = floorf(ysA);
            int   yA  = (int)fA;
            float w1A = ysA - fA, w0A = 1.0f - w1A;

            float ysB = (float)yc - sv.y;
            float fB  = floorf(ysB);
            int   yB  = (int)fB;
            float w1B = ysB - fB, w0B = 1.0f - w1B;

            #pragma unroll
            for (int s2 = 0; s2 < 2; s2++) {
                const int ocb = ws2*32 + s2*16;
                const int oc0 = ocb + g, oc1 = ocb + g + 8;
                const float* c0 = g_C2 + ((long)(b*CH + oc0))*C2ROWS*WID + x;
                const float* c1 = g_C2 + ((long)(b*CH + oc1))*C2ROWS*WID + x;

                float A0 = (yA >= -1) ? __ldg(c0 + (yA+1)*WID)     : 0.0f;
                float A1 = (yA >= -2) ? __ldg(c0 + (yA+2)*WID)     : 0.0f;
                float B0 = (yB >= -1) ? __ldg(c0 + (yB+1)*WID + 1) : 0.0f;
                float B1 = (yB >= -2) ? __ldg(c0 + (yB+2)*WID + 1) : 0.0f;
                float r00 = fminf(acc[s2][nf][0], w0A*A0 + w1A*A1);
                float r01 = fminf(acc[s2][nf][1], w0B*B0 + w1B*B1);

                float C0 = (yA >= -1) ? __ldg(c1 + (yA+1)*WID)     : 0.0f;
                float C1 = (yA >= -2) ? __ldg(c1 + (yA+2)*WID)     : 0.0f;
                float D0 = (yB >= -1) ? __ldg(c1 + (yB+1)*WID + 1) : 0.0f;
                float D1 = (yB >= -2) ? __ldg(c1 + (yB+2)*WID + 1) : 0.0f;
                float r10 = fminf(acc[s2][nf][2], w0A*C0 + w1A*C1);
                float r11 = fminf(acc[s2][nf][3], w0B*D0 + w1B*D1);

                float* o0 = Out + ((long)(b*CH + oc0))*HW + yc*WID + x;
                float* o1 = Out + ((long)(b*CH + oc1))*HW + yc*WID + x;
                *(float2*)o0 = make_float2(r00, r01);
                *(float2*)o1 = make_float2(r10, r11);
            }
        }
    }
}

// ---------------------------------------------------------------------------
extern "C" void kernel_launch(void* const* d_in, const int* in_sizes, int n_in,
                              void* d_out, int out_size) {
    const float* X  = (const float*)d_in[0];   // [4,64,256,256]
    const float* Wg = (const float*)d_in[1];   // [64,64,3,3]
    float* Out = (float*)d_out;                // [4,64,256,256]

    wt_kernel<<<(CH*CH*9 + 255)/256, 256>>>(Wg);
    {
        long tot = (long)BATCH*HW*8;
        prep_kernel<<<(int)((tot + 255)/256), 256>>>(X);
    }

    __nv_bfloat16 *xh, *xl, *zh, *zl;
    cudaGetSymbolAddress((void**)&xh, g_Xh);
    cudaGetSymbolAddress((void**)&xl, g_Xl);
    cudaGetSymbolAddress((void**)&zh, g_Zh);
    cudaGetSymbolAddress((void**)&zl, g_Zl);

    // C2 = conv3x3(x2), center rows -1..255
    {
        dim3 grid(WID/NPX, C2ROWS, BATCH);
        conv_mma_kernel<1><<<grid, 128>>>(zh, zl, nullptr);
    }
    // upper conv on X with fused interp/min epilogue -> Out
    {
        dim3 grid(WID/NPX, H, BATCH);
        conv_mma_kernel<0><<<grid, 128>>>(xh, xl, Out);
    }
}

// round 17
// speedup vs baseline: 1.5179x; 1.5179x over previous
#include <cuda_runtime.h>
#include <cuda_bf16.h>
#include <cstdint>

#define BATCH 4
#define CH    64
#define H     256
#define WID   256
#define HW    (H*WID)
#define CHW   (CH*HW)
#define C2ROWS 257          // center rows -1..255 stored at index yc+1
#define NPX   128           // pixels per block (N tile)
#define RS    24            // smem row stride in halves (48B -> conflict-free ldmatrix)

// scratch (allocation-free: __device__ globals)
__device__ float g_s[BATCH*HW];                    // per-pixel vertical shift s
__device__ float g_C2[BATCH*CH*C2ROWS*WID];        // conv3x3(x2) at rows -1..255
// channel-last bf16 hi/lo inputs: [b][y][x][c]
__device__ __align__(16) __nv_bfloat16 g_Xh[BATCH*HW*CH];
__device__ __align__(16) __nv_bfloat16 g_Xl[BATCH*HW*CH];
__device__ __align__(16) __nv_bfloat16 g_Zh[BATCH*HW*CH];
__device__ __align__(16) __nv_bfloat16 g_Zl[BATCH*HW*CH];
// weights as per-lane mma A fragments: [cc][tap][slice16][lane] -> uint4
__device__ __align__(16) __nv_bfloat16 g_Wah[4*9*4*32*8];
__device__ __align__(16) __nv_bfloat16 g_Wal[4*9*4*32*8];

// ---------------------------------------------------------------------------
__device__ __forceinline__ void mma16816(float* d, const uint32_t* a, uint32_t b0, uint32_t b1) {
    asm volatile(
        "mma.sync.aligned.m16n8k16.row.col.f32.bf16.bf16.f32 "
        "{%0,%1,%2,%3}, {%4,%5,%6,%7}, {%8,%9}, {%0,%1,%2,%3};\n"
        : "+f"(d[0]), "+f"(d[1]), "+f"(d[2]), "+f"(d[3])
        : "r"(a[0]), "r"(a[1]), "r"(a[2]), "r"(a[3]), "r"(b0), "r"(b1));
}

__device__ __forceinline__ void ldsm4(uint32_t* r, uint32_t addr) {
    asm volatile("ldmatrix.sync.aligned.m8n8.x4.shared.b16 {%0,%1,%2,%3}, [%4];"
        : "=r"(r[0]), "=r"(r[1]), "=r"(r[2]), "=r"(r[3]) : "r"(addr));
}

// ---------------------------------------------------------------------------
// Kernel W: split weights into bf16 hi/lo, scatter into per-lane A fragments
// ---------------------------------------------------------------------------
__global__ __launch_bounds__(256) void wt_kernel(const float* __restrict__ Wg) {
    int i = blockIdx.x * 256 + threadIdx.x;
    if (i >= CH*CH*9) return;
    int oc  = i / (CH*9);
    int rem = i - oc*CH*9;
    int c   = rem / 9;
    int tap = rem - c*9;
    float wv = Wg[i];
    __nv_bfloat16 h = __float2bfloat16(wv);
    __nv_bfloat16 l = __float2bfloat16(wv - __bfloat162float(h));

    int sl   = oc >> 4;           // m16 slice index 0..3
    int ocw  = oc & 15;
    int g    = ocw & 7;
    int hi8  = ocw >> 3;
    int cc   = c >> 4;
    int cp   = c & 15;
    int tig  = (cp >> 1) & 3;
    int khalf= cp >> 3;
    int pair = cp & 1;
    int reg  = hi8 + 2*khalf;
    int lane = g*4 + tig;
    int dst  = ((((cc*9 + tap)*4 + sl)*32 + lane)*4 + reg)*2 + pair;
    g_Wah[dst] = h;
    g_Wal[dst] = l;
}

// ---------------------------------------------------------------------------
// Kernel A (coalesced): 8 threads per pixel, each owning 8 channels.
// ---------------------------------------------------------------------------
__global__ __launch_bounds__(256) void prep_kernel(const float* __restrict__ X) {
    long idx = (long)blockIdx.x * 256 + threadIdx.x;
    if (idx >= (long)BATCH*HW*8) return;
    int pix = (int)(idx >> 3);
    int cg  = (int)(idx & 7);
    int b   = pix / HW;
    int rem = pix - b*HW;
    int y   = rem / WID;
    int x   = rem - y*WID;

    const float* Xpix = X + (long)b*CHW + y*WID + x;
    const float* Xc = Xpix + (long)cg*8*HW;

    float a[8];
    #pragma unroll
    for (int j = 0; j < 8; j++) a[j] = __ldg(Xc + (long)j*HW);

    float m = a[0];
    #pragma unroll
    for (int j = 1; j < 8; j++) m = fmaxf(m, a[j]);
    m = fmaxf(m, __shfl_xor_sync(0xffffffffu, m, 1));
    m = fmaxf(m, __shfl_xor_sync(0xffffffffu, m, 2));
    m = fmaxf(m, __shfl_xor_sync(0xffffffffu, m, 4));

    float depth = fminf(fmaxf(m, 1.0f), 50.0f);
    float s = 50.0f / (2.0f * depth);
    if (cg == 0) g_s[pix] = s;

    float ys = (float)y - s;
    float fy = floorf(ys);
    int   y0 = (int)fy;
    float w1 = ys - fy;
    float w0 = 1.0f - w1;

    bool ok0 = (y0   >= 0) && (y0   < H);
    bool ok1 = (y0+1 >= 0) && (y0+1 < H);
    const float* P0 = X + (long)b*CHW + (long)(ok0 ? y0   : 0)*WID + x + (long)cg*8*HW;
    const float* P1 = X + (long)b*CHW + (long)(ok1 ? y0+1 : 0)*WID + x + (long)cg*8*HW;

    __nv_bfloat162 xh[4], xl[4], zh[4], zl[4];
    #pragma unroll
    for (int j = 0; j < 4; j++) {
        float a0 = a[2*j], a1 = a[2*j+1];
        float p0 = ok0 ? __ldg(P0 + (long)(2*j)*HW)   : 0.0f;
        float p1 = ok0 ? __ldg(P0 + (long)(2*j+1)*HW) : 0.0f;
        float q0 = ok1 ? __ldg(P1 + (long)(2*j)*HW)   : 0.0f;
        float q1 = ok1 ? __ldg(P1 + (long)(2*j+1)*HW) : 0.0f;
        float v0 = w0*p0 + w1*q0;
        float v1 = w0*p1 + w1*q1;

        __nv_bfloat16 ah0 = __float2bfloat16(a0);
        __nv_bfloat16 ah1 = __float2bfloat16(a1);
        __nv_bfloat16 vh0 = __float2bfloat16(v0);
        __nv_bfloat16 vh1 = __float2bfloat16(v1);
        xh[j] = __nv_bfloat162(ah0, ah1);
        xl[j] = __nv_bfloat162(__float2bfloat16(a0 - __bfloat162float(ah0)),
                               __float2bfloat16(a1 - __bfloat162float(ah1)));
        zh[j] = __nv_bfloat162(vh0, vh1);
        zl[j] = __nv_bfloat162(__float2bfloat16(v0 - __bfloat162float(vh0)),
                               __float2bfloat16(v1 - __bfloat162float(vh1)));
    }
    const long ob = (long)pix * CH + cg*8;
    *(uint4*)(g_Xh + ob) = *(uint4*)xh;
    *(uint4*)(g_Xl + ob) = *(uint4*)xl;
    *(uint4*)(g_Zh + ob) = *(uint4*)zh;
    *(uint4*)(g_Zl + ob) = *(uint4*)zl;
}

// ---------------------------------------------------------------------------
// Tensor-core conv: block = 64 oc x 128 px, 4 warps m32n64, 16 warps/SM target.
// All global addressing via 32-bit byte offsets off hoisted base pointers.
// MODE 1: in = Zh/Zl, yc in [-1,255], store C2 at row index yc+1.
// MODE 0: in = Xh/Xl, yc in [0,255], fused interp+min epilogue -> Out.
// ---------------------------------------------------------------------------
template<int MODE>
__global__ __launch_bounds__(128, 4) void conv_mma_kernel(const __nv_bfloat16* __restrict__ Ih,
                                                          const __nv_bfloat16* __restrict__ Il,
                                                          float* __restrict__ Out) {
    __shared__ __align__(16) __nv_bfloat16 sBh[3][NPX+2][RS];
    __shared__ __align__(16) __nv_bfloat16 sBl[3][NPX+2][RS];

    const int t    = threadIdx.x;
    const int w    = t >> 5;
    const int lane = t & 31;
    const int ws2  = w & 1;            // oc slice of 32
    const int pxb  = (w >> 1) * 64;    // px half base

    const int x0 = blockIdx.x * NPX;
    const int yc = MODE ? ((int)blockIdx.y - 1) : (int)blockIdx.y;
    const int b  = blockIdx.z;

    float acc[2][8][4];
    #pragma unroll
    for (int s2 = 0; s2 < 2; s2++)
        #pragma unroll
        for (int nf = 0; nf < 8; nf++)
            #pragma unroll
            for (int k = 0; k < 4; k++) acc[s2][nf][k] = 0.0f;

    const int rowadd = ((lane >> 4) & 1) * 8 + (lane & 7);
    const int coladd = ((lane >> 3) & 1) * 8;
    const uint32_t sbH = (uint32_t)__cvta_generic_to_shared(&sBh[0][0][0]);
    const uint32_t sbL = (uint32_t)__cvta_generic_to_shared(&sBl[0][0][0]);
    const uint32_t tb  = (uint32_t)(rowadd*RS + coladd) * 2;

    // hoisted 32-bit base offsets (all tensors < 512MB)
    const char* Ih8 = (const char*)Ih + (uint32_t)b*(uint32_t)(HW*CH*2);
    const char* Il8 = (const char*)Il + (uint32_t)b*(uint32_t)(HW*CH*2);

    for (int cc = 0; cc < 4; cc++) {
        __syncthreads();
        // ---- stage 16-ch chunk of 3 input rows ----
        {
            const uint4 z = make_uint4(0,0,0,0);
            // i = r*(NPX+2)+px, 390 entries, 128 threads -> ~3 iters
            for (int i = t; i < 3*(NPX+2); i += 128) {
                int r  = i / (NPX+2);
                int px = i - r*(NPX+2);
                int row = yc + r - 1;
                int col = x0 + px - 1;
                uint4 h0 = z, h1 = z, l0 = z, l1 = z;
                if (((unsigned)row < (unsigned)H) & ((unsigned)col < (unsigned)WID)) {
                    uint32_t off = ((uint32_t)(row*WID + col)*(uint32_t)CH + (uint32_t)cc*16)*2u;
                    const uint4* ph = (const uint4*)(Ih8 + off);
                    const uint4* pl = (const uint4*)(Il8 + off);
                    h0 = __ldg(ph);  h1 = __ldg(ph + 1);
                    l0 = __ldg(pl);  l1 = __ldg(pl + 1);
                }
                uint32_t so = (uint32_t)(r*(NPX+2) + px)*(RS*2);
                *(uint4*)((char*)&sBh[0][0][0] + so)      = h0;
                *(uint4*)((char*)&sBh[0][0][0] + so + 16) = h1;
                *(uint4*)((char*)&sBl[0][0][0] + so)      = l0;
                *(uint4*)((char*)&sBl[0][0][0] + so + 16) = l1;
            }
        }
        __syncthreads();

        #pragma unroll
        for (int tap = 0; tap < 9; tap++) {
            const int ky = tap / 3;
            const int kx = tap - ky*3;

            uint32_t ah[2][4], al[2][4];
            #pragma unroll
            for (int s2 = 0; s2 < 2; s2++) {
                const int aidx = ((cc*9 + tap)*4 + ws2*2 + s2)*32 + lane;
                uint4 a4h = __ldg((const uint4*)g_Wah + aidx);
                uint4 a4l = __ldg((const uint4*)g_Wal + aidx);
                ah[s2][0]=a4h.x; ah[s2][1]=a4h.y; ah[s2][2]=a4h.z; ah[s2][3]=a4h.w;
                al[s2][0]=a4l.x; al[s2][1]=a4l.y; al[s2][2]=a4l.z; al[s2][3]=a4l.w;
            }

            #pragma unroll
            for (int P = 0; P < 4; P++) {
                const uint32_t off = tb
                    + (uint32_t)((ky*(NPX+2) + kx + pxb + P*16)*RS)*2;
                uint32_t bh[4], bl[4];
                ldsm4(bh, sbH + off);
                ldsm4(bl, sbL + off);
                const int nf0 = P*2, nf1 = P*2 + 1;
                #pragma unroll
                for (int s2 = 0; s2 < 2; s2++) {
                    mma16816(acc[s2][nf0], ah[s2], bh[0], bh[1]);
                    mma16816(acc[s2][nf0], ah[s2], bl[0], bl[1]);
                    mma16816(acc[s2][nf0], al[s2], bh[0], bh[1]);
                    mma16816(acc[s2][nf1], ah[s2], bh[2], bh[3]);
                    mma16816(acc[s2][nf1], ah[s2], bl[2], bl[3]);
                    mma16816(acc[s2][nf1], al[s2], bh[2], bh[3]);
                }
            }
        }
    }

    // ---- epilogue ----
    const int g    = lane >> 2;
    const int tig  = lane & 3;
    if (MODE == 1) {
        const uint32_t rr = (uint32_t)(yc + 1);        // 0..256
        char* c2b = (char*)g_C2 + (uint32_t)b*(uint32_t)(CH*C2ROWS*WID*4);
        #pragma unroll
        for (int s2 = 0; s2 < 2; s2++) {
            const int ocb = ws2*32 + s2*16;
            #pragma unroll
            for (int nf = 0; nf < 8; nf++) {
                const int col = pxb + (nf >> 1)*16 + (nf & 1)*8 + tig*2;
                uint32_t o0 = (((uint32_t)(ocb + g    )*C2ROWS + rr)*WID + (uint32_t)(x0 + col))*4u;
                uint32_t o1 = (((uint32_t)(ocb + g + 8)*C2ROWS + rr)*WID + (uint32_t)(x0 + col))*4u;
                *(float2*)(c2b + o0) = make_float2(acc[s2][nf][0], acc[s2][nf][1]);
                *(float2*)(c2b + o1) = make_float2(acc[s2][nf][2], acc[s2][nf][3]);
            }
        }
    } else {
        const char* c2b = (const char*)g_C2 + (uint32_t)b*(uint32_t)(CH*C2ROWS*WID*4);
        char* ob = (char*)Out + (uint32_t)b*(uint32_t)(CHW*4);
        #pragma unroll
        for (int nf = 0; nf < 8; nf++) {
            const int col = pxb + (nf >> 1)*16 + (nf & 1)*8 + tig*2;
            const int x = x0 + col;
            float2 sv = *(const float2*)&g_s[b*HW + yc*WID + x];

            float ysA = (float)yc - sv.x;
            float fA  = floorf(ysA);
            int   yA  = (int)fA;
            float w1A = ysA - fA, w0A = 1.0f - w1A;

            float ysB = (float)yc - sv.y;
            float fB  = floorf(ysB);
            int   yB  = (int)fB;
            float w1B = ysB - fB, w0B = 1.0f - w1B;

            #pragma unroll
            for (int s2 = 0; s2 < 2; s2++) {
                const int ocb = ws2*32 + s2*16;
                #pragma unroll
                for (int hh = 0; hh < 2; hh++) {
                    const int oc = ocb + g + hh*8;
                    const float* cc0 = (const float*)(c2b + (uint32_t)oc*(uint32_t)(C2ROWS*WID*4)) + x;
                    float A0 = (yA >= -1) ? __ldg(cc0 + (yA+1)*WID)     : 0.0f;
                    float A1 = (yA >= -2) ? __ldg(cc0 + (yA+2)*WID)     : 0.0f;
                    float B0 = (yB >= -1) ? __ldg(cc0 + (yB+1)*WID + 1) : 0.0f;
                    float B1 = (yB >= -2) ? __ldg(cc0 + (yB+2)*WID + 1) : 0.0f;
                    float r0 = fminf(acc[s2][nf][hh*2],   w0A*A0 + w1A*A1);
                    float r1 = fminf(acc[s2][nf][hh*2+1], w0B*B0 + w1B*B1);
                    *(float2*)(ob + ((uint32_t)oc*(uint32_t)HW + (uint32_t)(yc*WID + x))*4u)
                        = make_float2(r0, r1);
                }
            }
        }
    }
}

// ---------------------------------------------------------------------------
extern "C" void kernel_launch(void* const* d_in, const int* in_sizes, int n_in,
                              void* d_out, int out_size) {
    const float* X  = (const float*)d_in[0];   // [4,64,256,256]
    const float* Wg = (const float*)d_in[1];   // [64,64,3,3]
    float* Out = (float*)d_out;                // [4,64,256,256]

    wt_kernel<<<(CH*CH*9 + 255)/256, 256>>>(Wg);
    {
        long tot = (long)BATCH*HW*8;
        prep_kernel<<<(int)((tot + 255)/256), 256>>>(X);
    }

    __nv_bfloat16 *xh, *xl, *zh, *zl;
    cudaGetSymbolAddress((void**)&xh, g_Xh);
    cudaGetSymbolAddress((void**)&xl, g_Xl);
    cudaGetSymbolAddress((void**)&zh, g_Zh);
    cudaGetSymbolAddress((void**)&zl, g_Zl);

    // C2 = conv3x3(x2), center rows -1..255
    {
        dim3 grid(WID/NPX, C2ROWS, BATCH);
        conv_mma_kernel<1><<<grid, 128>>>(zh, zl, nullptr);
    }
    // upper conv on X with fused interp/min epilogue -> Out
    {
        dim3 grid(WID/NPX, H, BATCH);
        conv_mma_kernel<0><<<grid, 128>>>(xh, xl, Out);
    }
}